// round 8
// baseline (speedup 1.0000x reference)
#include <cuda_runtime.h>
#include <cuda_bf16.h>
#include <stdint.h>
#include <math.h>

#define B 2
#define S 2048
#define E 1024
#define H 16
#define D 64
#define MROWS (B*S)                   // 4096
#define KPAIRS 512                    // 1024 floats -> 512 bf16 pairs
#define OUT_ELEMS (B*S*E)             // 4194304
#define ATTN_ELEMS ((size_t)B*H*S*S)  // 134217728

// ------------------------- device scratch (no runtime alloc) -----------------
__device__ uint32_t g_xq_hi[MROWS*KPAIRS], g_xq_lo[MROWS*KPAIRS];
__device__ uint32_t g_xk_hi[MROWS*KPAIRS], g_xk_lo[MROWS*KPAIRS];
__device__ uint32_t g_xv_hi[MROWS*KPAIRS], g_xv_lo[MROWS*KPAIRS];
__device__ uint32_t g_wq_hi[E*KPAIRS],  g_wq_lo[E*KPAIRS];
__device__ uint32_t g_wk_hi[E*KPAIRS],  g_wk_lo[E*KPAIRS];
__device__ uint32_t g_wv_hi[E*KPAIRS],  g_wv_lo[E*KPAIRS];
__device__ uint32_t g_wo_hi[E*KPAIRS],  g_wo_lo[E*KPAIRS];
__device__ uint32_t g_qhi[B*H*S*(D/2)], g_qlo[B*H*S*(D/2)];   // packed (b,h,s,d/2)
__device__ uint32_t g_khi[B*H*S*(D/2)], g_klo[B*H*S*(D/2)];
__device__ float    g_v[B*H*S*D];                              // fp32 (b,h,s,d)
__device__ uint32_t g_chi[MROWS*KPAIRS], g_clo[MROWS*KPAIRS];  // ctx packed (b,s,e/2)

// ------------------------------- helpers -------------------------------------
__device__ __forceinline__ void split_pack(float x0, float x1,
                                           uint32_t& hi, uint32_t& lo) {
    __nv_bfloat16 h0 = __float2bfloat16(x0);
    __nv_bfloat16 h1 = __float2bfloat16(x1);
    __nv_bfloat16 l0 = __float2bfloat16(x0 - __bfloat162float(h0));
    __nv_bfloat16 l1 = __float2bfloat16(x1 - __bfloat162float(h1));
    hi = ((uint32_t)__bfloat16_as_ushort(h1) << 16) | __bfloat16_as_ushort(h0);
    lo = ((uint32_t)__bfloat16_as_ushort(l1) << 16) | __bfloat16_as_ushort(l0);
}

__device__ __forceinline__ void mma_bf16(float* d, const uint32_t* a, const uint32_t* b) {
    asm volatile(
        "mma.sync.aligned.m16n8k16.row.col.f32.bf16.bf16.f32 "
        "{%0,%1,%2,%3},{%4,%5,%6,%7},{%8,%9},{%0,%1,%2,%3};\n"
        : "+f"(d[0]), "+f"(d[1]), "+f"(d[2]), "+f"(d[3])
        : "r"(a[0]), "r"(a[1]), "r"(a[2]), "r"(a[3]), "r"(b[0]), "r"(b[1]));
}

__device__ __forceinline__ void cp16(uint32_t saddr, const void* gptr) {
    asm volatile("cp.async.cg.shared.global [%0], [%1], 16;\n"
                 :: "r"(saddr), "l"(gptr));
}
#define CP_COMMIT() asm volatile("cp.async.commit_group;\n" ::: "memory")

// ------------------------- pack fp32 -> bf16 hi/lo pairs ---------------------
__global__ __launch_bounds__(256)
void pack3_kernel(const float* __restrict__ s0, const float* __restrict__ s1,
                  const float* __restrict__ s2,
                  uint32_t* __restrict__ h0, uint32_t* __restrict__ l0_,
                  uint32_t* __restrict__ h1, uint32_t* __restrict__ l1_,
                  uint32_t* __restrict__ h2, uint32_t* __restrict__ l2_,
                  int npairs)
{
    int i = blockIdx.x * 256 + threadIdx.x;
    if (i >= npairs) return;
    const float* src = (blockIdx.y == 0) ? s0 : (blockIdx.y == 1) ? s1 : s2;
    uint32_t* hi = (blockIdx.y == 0) ? h0 : (blockIdx.y == 1) ? h1 : h2;
    uint32_t* lo = (blockIdx.y == 0) ? l0_ : (blockIdx.y == 1) ? l1_ : l2_;
    float2 v = ((const float2*)src)[i];
    uint32_t h, l;
    split_pack(v.x, v.y, h, l);
    hi[i] = h; lo[i] = l;
}

__global__ __launch_bounds__(256)
void pack4_kernel(const float* __restrict__ s0, const float* __restrict__ s1,
                  const float* __restrict__ s2, const float* __restrict__ s3,
                  uint32_t* __restrict__ h0, uint32_t* __restrict__ l0_,
                  uint32_t* __restrict__ h1, uint32_t* __restrict__ l1_,
                  uint32_t* __restrict__ h2, uint32_t* __restrict__ l2_,
                  uint32_t* __restrict__ h3, uint32_t* __restrict__ l3_,
                  int npairs)
{
    int i = blockIdx.x * 256 + threadIdx.x;
    if (i >= npairs) return;
    const float* src = (blockIdx.y == 0) ? s0 : (blockIdx.y == 1) ? s1
                     : (blockIdx.y == 2) ? s2 : s3;
    uint32_t* hi = (blockIdx.y == 0) ? h0 : (blockIdx.y == 1) ? h1
                 : (blockIdx.y == 2) ? h2 : h3;
    uint32_t* lo = (blockIdx.y == 0) ? l0_ : (blockIdx.y == 1) ? l1_
                 : (blockIdx.y == 2) ? l2_ : l3_;
    float2 v = ((const float2*)src)[i];
    uint32_t h, l;
    split_pack(v.x, v.y, h, l);
    hi[i] = h; lo[i] = l;
}

// ------------------------------- GEMM ----------------------------------------
// C[m][n] = dot(A[m,:], W[n,:]) + bias[n], M=4096, N=1024, K=1024.
// cp.async double-buffered: 2 smem stages, prefetch chunk k+1 during mma of k.
#define STRG 36   // 32 pairs + pad
#define AH_O 0
#define AL_O (128*STRG)
#define WH_O (256*STRG)
#define WL_O (256*STRG + 64*STRG)
#define STAGE_W (384*STRG)                 // words per stage = 13824
#define SMEM_G (2*STAGE_W*4)               // 110592 bytes

template <int MODE>
__global__ __launch_bounds__(256)
void gemm_tc(const uint32_t* __restrict__ Ahi, const uint32_t* __restrict__ Alo,
             const uint32_t* __restrict__ Whi, const uint32_t* __restrict__ Wlo,
             const float* __restrict__ bias,
             float* __restrict__ outf,
             uint32_t* __restrict__ outhi, uint32_t* __restrict__ outlo,
             float scale)
{
    extern __shared__ uint32_t sg[];
    const uint32_t sbase = (uint32_t)__cvta_generic_to_shared(sg);

    const int t = threadIdx.x, lane = t & 31, g = lane >> 2, tg = lane & 3;
    const int warp = t >> 5, wm = warp >> 1, wn = warp & 1;
    const int rowBase = blockIdx.y * 128, colBase = blockIdx.x * 64;

    auto issue = [&](int kt, int st) {
        const int kp0g = kt * 32;
        const uint32_t sb = sbase + (uint32_t)st * (STAGE_W * 4);
        #pragma unroll
        for (int r = 0; r < 4; r++) {
            int idx = t + r * 256;
            int row = idx >> 3, c4 = (idx & 7) << 2;
            cp16(sb + (AH_O + row*STRG + c4) * 4,
                 Ahi + (size_t)(rowBase + row) * KPAIRS + kp0g + c4);
            cp16(sb + (AL_O + row*STRG + c4) * 4,
                 Alo + (size_t)(rowBase + row) * KPAIRS + kp0g + c4);
        }
        #pragma unroll
        for (int r = 0; r < 2; r++) {
            int idx = t + r * 256;
            int row = idx >> 3, c4 = (idx & 7) << 2;
            cp16(sb + (WH_O + row*STRG + c4) * 4,
                 Whi + (size_t)(colBase + row) * KPAIRS + kp0g + c4);
            cp16(sb + (WL_O + row*STRG + c4) * 4,
                 Wlo + (size_t)(colBase + row) * KPAIRS + kp0g + c4);
        }
        CP_COMMIT();
    };

    float acc[2][4][4] = {};

    issue(0, 0);
    issue(1, 1);

    for (int kt = 0; kt < 16; kt++) {
        if (kt < 15) asm volatile("cp.async.wait_group 1;\n" ::: "memory");
        else         asm volatile("cp.async.wait_group 0;\n" ::: "memory");
        __syncthreads();

        const uint32_t* Ah = sg + (kt & 1) * STAGE_W + AH_O;
        const uint32_t* Al = sg + (kt & 1) * STAGE_W + AL_O;
        const uint32_t* Wh = sg + (kt & 1) * STAGE_W + WH_O;
        const uint32_t* Wl = sg + (kt & 1) * STAGE_W + WL_O;

        #pragma unroll
        for (int ks = 0; ks < 4; ks++) {
            const int kp0 = ks * 8;
            uint32_t ah[2][4], al[2][4];
            #pragma unroll
            for (int mt = 0; mt < 2; mt++) {
                int r0 = (wm*32 + mt*16 + g) * STRG + kp0 + tg;
                int r8 = r0 + 8 * STRG;
                ah[mt][0] = Ah[r0]; ah[mt][1] = Ah[r8];
                ah[mt][2] = Ah[r0+4]; ah[mt][3] = Ah[r8+4];
                al[mt][0] = Al[r0]; al[mt][1] = Al[r8];
                al[mt][2] = Al[r0+4]; al[mt][3] = Al[r8+4];
            }
            #pragma unroll
            for (int nt = 0; nt < 4; nt++) {
                int nb = (wn*32 + nt*8 + g) * STRG + kp0 + tg;
                uint32_t bh[2] = { Wh[nb], Wh[nb+4] };
                uint32_t bl[2] = { Wl[nb], Wl[nb+4] };
                #pragma unroll
                for (int mt = 0; mt < 2; mt++) {
                    mma_bf16(acc[mt][nt], ah[mt], bh);
                    mma_bf16(acc[mt][nt], al[mt], bh);
                    mma_bf16(acc[mt][nt], ah[mt], bl);
                }
            }
        }
        __syncthreads();
        if (kt + 2 < 16) issue(kt + 2, kt & 1);
    }

    #pragma unroll
    for (int mt = 0; mt < 2; mt++) {
        #pragma unroll
        for (int nt = 0; nt < 4; nt++) {
            int m0 = rowBase + wm*32 + mt*16 + g;
            int n  = colBase + wn*32 + nt*8 + 2*tg;
            float b0 = bias[n], b1 = bias[n+1];
            float v00 = (acc[mt][nt][0] + b0) * scale;
            float v01 = (acc[mt][nt][1] + b1) * scale;
            float v10 = (acc[mt][nt][2] + b0) * scale;
            float v11 = (acc[mt][nt][3] + b1) * scale;
            if (MODE == 0) {
                *(float2*)(outf + (size_t)m0 * 1024 + n)       = make_float2(v00, v01);
                *(float2*)(outf + (size_t)(m0 + 8) * 1024 + n) = make_float2(v10, v11);
            } else if (MODE == 1) {
                int hh = n >> 6, dp = (n >> 1) & 31;
                {
                    int bb = m0 >> 11, ss = m0 & 2047;
                    size_t p = ((size_t)(bb*H + hh)*S + ss) * (D/2) + dp;
                    uint32_t hw, lw; split_pack(v00, v01, hw, lw);
                    outhi[p] = hw; outlo[p] = lw;
                }
                {
                    int m8 = m0 + 8, bb = m8 >> 11, ss = m8 & 2047;
                    size_t p = ((size_t)(bb*H + hh)*S + ss) * (D/2) + dp;
                    uint32_t hw, lw; split_pack(v10, v11, hw, lw);
                    outhi[p] = hw; outlo[p] = lw;
                }
            } else { // MODE 2
                int hh = n >> 6, d = n & 63;
                {
                    int bb = m0 >> 11, ss = m0 & 2047;
                    *(float2*)(outf + ((size_t)(bb*H + hh)*S + ss) * D + d) = make_float2(v00, v01);
                }
                {
                    int m8 = m0 + 8, bb = m8 >> 11, ss = m8 & 2047;
                    *(float2*)(outf + ((size_t)(bb*H + hh)*S + ss) * D + d) = make_float2(v10, v11);
                }
            }
        }
    }
}

// ------------------------------- attention -----------------------------------
// Phase 1: flash sweep, spill raw scores. Phase 2 (fused): re-read own spill
// (L2-resident), apply exp(s-m)/l, overwrite with final probabilities.
#define STRA 36   // 32 pairs + pad (uint32)
#define STRP 68   // Ps fp32 stride
#define SMEM_A (8*64*STRA*4 + 64*STRP*4 + 3*64*4)

__global__ __launch_bounds__(256)
void attn_tc(const uint32_t* __restrict__ qhi, const uint32_t* __restrict__ qlo,
             const uint32_t* __restrict__ khi, const uint32_t* __restrict__ klo,
             const float* __restrict__ vf,
             float* __restrict__ attn_out,
             uint32_t* __restrict__ ctxhi, uint32_t* __restrict__ ctxlo,
             int write_attn)
{
    extern __shared__ uint32_t sa[];
    uint32_t* Qh = sa;
    uint32_t* Ql = Qh + 64*STRA;
    uint32_t* Kh = Ql + 64*STRA;
    uint32_t* Kl = Kh + 64*STRA;
    uint32_t* Vh = Kl + 64*STRA;   // transposed [d][keypair]
    uint32_t* Vl = Vh + 64*STRA;
    uint32_t* Ph = Vl + 64*STRA;
    uint32_t* Pl = Ph + 64*STRA;
    float*    Ps = (float*)(Pl + 64*STRA);
    float* m_run = Ps + 64*STRP;
    float* l_run = m_run + 64;
    float* fac   = l_run + 64;

    const int qt = blockIdx.x, h = blockIdx.y, b = blockIdx.z;
    const int bh = b * H + h;
    const int t = threadIdx.x, lane = t & 31, g = lane >> 2, tg = lane & 3;
    const int warp = t >> 5, wm = warp >> 1, wn = warp & 1;

    {
        const size_t qb = ((size_t)bh * S + qt * 64) * (D/2);
        #pragma unroll
        for (int r = 0; r < 2; r++) {
            int idx = t + r * 256;
            int row = idx >> 3, c4 = (idx & 7) << 2;
            *(uint4*)&Qh[row*STRA + c4] = *(const uint4*)(qhi + qb + row*(D/2) + c4);
            *(uint4*)&Ql[row*STRA + c4] = *(const uint4*)(qlo + qb + row*(D/2) + c4);
        }
    }
    if (t < 64) { m_run[t] = -1e30f; l_run[t] = 0.0f; }

    float cacc[4][4] = {};

    for (int kt = 0; kt < S/64; kt++) {
        __syncthreads();
        {
            const size_t kb = ((size_t)bh * S + kt * 64) * (D/2);
            #pragma unroll
            for (int r = 0; r < 2; r++) {
                int idx = t + r * 256;
                int row = idx >> 3, c4 = (idx & 7) << 2;
                *(uint4*)&Kh[row*STRA + c4] = *(const uint4*)(khi + kb + row*(D/2) + c4);
                *(uint4*)&Kl[row*STRA + c4] = *(const uint4*)(klo + kb + row*(D/2) + c4);
            }
        }
        {
            const float* vb = vf + ((size_t)bh * S + kt * 64) * D;
            #pragma unroll
            for (int r = 0; r < 8; r++) {
                int slot = t + r * 256;
                int d = slot & 63, kp = slot >> 6;
                float v0 = vb[(2*kp)   * D + d];
                float v1 = vb[(2*kp+1) * D + d];
                uint32_t hw, lw; split_pack(v0, v1, hw, lw);
                Vh[d*STRA + kp] = hw;
                Vl[d*STRA + kp] = lw;
            }
        }
        __syncthreads();

        // S = Q @ K^T (q pre-scaled)
        float sacc[4][4] = {};
        #pragma unroll
        for (int ks = 0; ks < 4; ks++) {
            const int kp0 = ks * 8;
            uint32_t ah[4], al[4];
            int r0 = (wm*16 + g) * STRA + kp0 + tg;
            int r8 = r0 + 8 * STRA;
            ah[0] = Qh[r0]; ah[1] = Qh[r8]; ah[2] = Qh[r0+4]; ah[3] = Qh[r8+4];
            al[0] = Ql[r0]; al[1] = Ql[r8]; al[2] = Ql[r0+4]; al[3] = Ql[r8+4];
            #pragma unroll
            for (int nt = 0; nt < 4; nt++) {
                int nb = (wn*32 + nt*8 + g) * STRA + kp0 + tg;
                uint32_t bhf[2] = { Kh[nb], Kh[nb+4] };
                uint32_t blf[2] = { Kl[nb], Kl[nb+4] };
                mma_bf16(sacc[nt], ah, bhf);
                mma_bf16(sacc[nt], al, bhf);
                mma_bf16(sacc[nt], ah, blf);
            }
        }
        #pragma unroll
        for (int nt = 0; nt < 4; nt++) {
            int rr = (wm*16 + g) * STRP + wn*32 + nt*8 + 2*tg;
            Ps[rr]            = sacc[nt][0];
            Ps[rr + 1]        = sacc[nt][1];
            Ps[rr + 8*STRP]   = sacc[nt][2];
            Ps[rr + 8*STRP+1] = sacc[nt][3];
        }
        __syncthreads();

        // spill raw scores
        if (write_attn) {
            #pragma unroll
            for (int r = 0; r < 4; r++) {
                int idx = t + r * 256;
                int row = idx >> 4, c4 = (idx & 15) << 2;
                float4 v = *(const float4*)(Ps + row*STRP + c4);
                *(float4*)(attn_out + (size_t)bh*S*S
                           + (size_t)(qt*64 + row) * S + kt*64 + c4) = v;
            }
        }
        // online softmax: 4 threads per row; write split P
        {
            const int q = t >> 2, gg = t & 3;
            const float* prow = Ps + q * STRP;
            float mx = -1e30f;
            #pragma unroll
            for (int c = gg*16; c < gg*16 + 16; c++) mx = fmaxf(mx, prow[c]);
            mx = fmaxf(mx, __shfl_xor_sync(0xffffffffu, mx, 1));
            mx = fmaxf(mx, __shfl_xor_sync(0xffffffffu, mx, 2));
            const float m_old = m_run[q];
            const float m_new = fmaxf(m_old, mx);
            const float f = __expf(m_old - m_new);
            float sum = 0.0f;
            #pragma unroll
            for (int cp = 0; cp < 8; cp++) {
                float p0 = __expf(prow[gg*16 + 2*cp]     - m_new);
                float p1 = __expf(prow[gg*16 + 2*cp + 1] - m_new);
                sum += p0 + p1;
                uint32_t hw, lw; split_pack(p0, p1, hw, lw);
                Ph[q*STRA + gg*8 + cp] = hw;
                Pl[q*STRA + gg*8 + cp] = lw;
            }
            sum += __shfl_xor_sync(0xffffffffu, sum, 1);
            sum += __shfl_xor_sync(0xffffffffu, sum, 2);
            if (gg == 0) {
                m_run[q] = m_new;
                l_run[q] = l_run[q] * f + sum;
                fac[q]   = f;
            }
        }
        __syncthreads();

        // rescale + ctx += P @ V
        {
            float f0 = fac[wm*16 + g];
            float f8 = fac[wm*16 + g + 8];
            #pragma unroll
            for (int nt = 0; nt < 4; nt++) {
                cacc[nt][0] *= f0; cacc[nt][1] *= f0;
                cacc[nt][2] *= f8; cacc[nt][3] *= f8;
            }
        }
        #pragma unroll
        for (int ks = 0; ks < 4; ks++) {
            const int kp0 = ks * 8;
            uint32_t ah[4], al[4];
            int r0 = (wm*16 + g) * STRA + kp0 + tg;
            int r8 = r0 + 8 * STRA;
            ah[0] = Ph[r0]; ah[1] = Ph[r8]; ah[2] = Ph[r0+4]; ah[3] = Ph[r8+4];
            al[0] = Pl[r0]; al[1] = Pl[r8]; al[2] = Pl[r0+4]; al[3] = Pl[r8+4];
            #pragma unroll
            for (int nt = 0; nt < 4; nt++) {
                int nb = (wn*32 + nt*8 + g) * STRA + kp0 + tg;
                uint32_t bhf[2] = { Vh[nb], Vh[nb+4] };
                uint32_t blf[2] = { Vl[nb], Vl[nb+4] };
                mma_bf16(cacc[nt], ah, bhf);
                mma_bf16(cacc[nt], al, bhf);
                mma_bf16(cacc[nt], ah, blf);
            }
        }
    }

    // epilogue: normalize, split-pack ctx into (b,s,e/2)
    {
        float inv0 = 1.0f / l_run[wm*16 + g];
        float inv8 = 1.0f / l_run[wm*16 + g + 8];
        int s0 = qt*64 + wm*16 + g;
        #pragma unroll
        for (int nt = 0; nt < 4; nt++) {
            int pp = h * 32 + wn*16 + nt*4 + tg;
            uint32_t hw, lw;
            split_pack(cacc[nt][0]*inv0, cacc[nt][1]*inv0, hw, lw);
            size_t p0 = ((size_t)b*S + s0) * KPAIRS + pp;
            ctxhi[p0] = hw; ctxlo[p0] = lw;
            split_pack(cacc[nt][2]*inv8, cacc[nt][3]*inv8, hw, lw);
            size_t p8 = ((size_t)b*S + s0 + 8) * KPAIRS + pp;
            ctxhi[p8] = hw; ctxlo[p8] = lw;
        }
    }

    if (!write_attn) return;

    // ---------------- phase 2: L2-resident normalize of own spill ------------
    __syncthreads();                         // global stores visible block-wide
    if (t < 64) fac[t] = 1.0f / l_run[t];    // reuse fac as inv-l
    __syncthreads();

    {
        float* base = attn_out + (size_t)bh*S*S + (size_t)(qt*64) * S;
        #pragma unroll 4
        for (int it = 0; it < 128; it++) {   // 32 kt-tiles x 4 rounds
            int idx = t + (it & 3) * 256;
            int row = idx >> 4, c4 = (idx & 15) << 2;
            float* p = base + (size_t)row * S + (it >> 2) * 64 + c4;
            const float m = m_run[row];
            const float invl = fac[row];
            float4 v = *(const float4*)p;
            v.x = __expf(v.x - m) * invl;
            v.y = __expf(v.y - m) * invl;
            v.z = __expf(v.z - m) * invl;
            v.w = __expf(v.w - m) * invl;
            *(float4*)p = v;
        }
    }
}

// --------------------------------- launch ------------------------------------
extern "C" void kernel_launch(void* const* d_in, const int* in_sizes, int n_in,
                              void* d_out, int out_size)
{
    const float* query = (const float*)d_in[0];
    const float* key   = (const float*)d_in[1];
    const float* value = (const float*)d_in[2];
    const float* Wq = (const float*)d_in[3];
    const float* bq = (const float*)d_in[4];
    const float* Wk = (const float*)d_in[5];
    const float* bk = (const float*)d_in[6];
    const float* Wv = (const float*)d_in[7];
    const float* bv = (const float*)d_in[8];
    const float* Wo = (const float*)d_in[9];
    const float* bo = (const float*)d_in[10];

    float* out_ptr = (float*)d_out;
    const int write_attn = (out_size >= (int)(OUT_ELEMS + ATTN_ELEMS)) ? 1 : 0;
    float* attn_ptr = out_ptr + OUT_ELEMS;

    void* xqh; cudaGetSymbolAddress(&xqh, g_xq_hi);
    void* xql; cudaGetSymbolAddress(&xql, g_xq_lo);
    void* xkh; cudaGetSymbolAddress(&xkh, g_xk_hi);
    void* xkl; cudaGetSymbolAddress(&xkl, g_xk_lo);
    void* xvh; cudaGetSymbolAddress(&xvh, g_xv_hi);
    void* xvl; cudaGetSymbolAddress(&xvl, g_xv_lo);
    void* wqh; cudaGetSymbolAddress(&wqh, g_wq_hi);
    void* wql; cudaGetSymbolAddress(&wql, g_wq_lo);
    void* wkh; cudaGetSymbolAddress(&wkh, g_wk_hi);
    void* wkl; cudaGetSymbolAddress(&wkl, g_wk_lo);
    void* wvh; cudaGetSymbolAddress(&wvh, g_wv_hi);
    void* wvl; cudaGetSymbolAddress(&wvl, g_wv_lo);
    void* woh; cudaGetSymbolAddress(&woh, g_wo_hi);
    void* wol; cudaGetSymbolAddress(&wol, g_wo_lo);
    void* qh;  cudaGetSymbolAddress(&qh,  g_qhi);
    void* ql;  cudaGetSymbolAddress(&ql,  g_qlo);
    void* kh;  cudaGetSymbolAddress(&kh,  g_khi);
    void* kl;  cudaGetSymbolAddress(&kl,  g_klo);
    void* vv;  cudaGetSymbolAddress(&vv,  g_v);
    void* ch;  cudaGetSymbolAddress(&ch,  g_chi);
    void* cl;  cudaGetSymbolAddress(&cl,  g_clo);

    const int npi = MROWS * KPAIRS;   // 2,097,152
    const int npw = E * KPAIRS;       // 524,288

    pack3_kernel<<<dim3(npi/256, 3), 256>>>(
        query, key, value,
        (uint32_t*)xqh, (uint32_t*)xql,
        (uint32_t*)xkh, (uint32_t*)xkl,
        (uint32_t*)xvh, (uint32_t*)xvl, npi);
    pack4_kernel<<<dim3(npw/256, 4), 256>>>(
        Wq, Wk, Wv, Wo,
        (uint32_t*)wqh, (uint32_t*)wql,
        (uint32_t*)wkh, (uint32_t*)wkl,
        (uint32_t*)wvh, (uint32_t*)wvl,
        (uint32_t*)woh, (uint32_t*)wol, npw);

    cudaFuncSetAttribute(gemm_tc<0>, cudaFuncAttributeMaxDynamicSharedMemorySize, SMEM_G);
    cudaFuncSetAttribute(gemm_tc<1>, cudaFuncAttributeMaxDynamicSharedMemorySize, SMEM_G);
    cudaFuncSetAttribute(gemm_tc<2>, cudaFuncAttributeMaxDynamicSharedMemorySize, SMEM_G);
    cudaFuncSetAttribute(attn_tc,    cudaFuncAttributeMaxDynamicSharedMemorySize, SMEM_A);

    dim3 gblk(256);
    dim3 ggrid(1024/64, MROWS/128);   // (16, 32)

    gemm_tc<1><<<ggrid, gblk, SMEM_G>>>((const uint32_t*)xqh, (const uint32_t*)xql,
                                        (const uint32_t*)wqh, (const uint32_t*)wql,
                                        bq, nullptr, (uint32_t*)qh, (uint32_t*)ql, 0.125f);
    gemm_tc<1><<<ggrid, gblk, SMEM_G>>>((const uint32_t*)xkh, (const uint32_t*)xkl,
                                        (const uint32_t*)wkh, (const uint32_t*)wkl,
                                        bk, nullptr, (uint32_t*)kh, (uint32_t*)kl, 1.0f);
    gemm_tc<2><<<ggrid, gblk, SMEM_G>>>((const uint32_t*)xvh, (const uint32_t*)xvl,
                                        (const uint32_t*)wvh, (const uint32_t*)wvl,
                                        bv, (float*)vv, nullptr, nullptr, 1.0f);

    dim3 agrid(S/64, H, B);
    attn_tc<<<agrid, gblk, SMEM_A>>>((const uint32_t*)qh, (const uint32_t*)ql,
                                     (const uint32_t*)kh, (const uint32_t*)kl,
                                     (const float*)vv,
                                     attn_ptr,
                                     (uint32_t*)ch, (uint32_t*)cl, write_attn);

    gemm_tc<0><<<ggrid, gblk, SMEM_G>>>((const uint32_t*)ch, (const uint32_t*)cl,
                                        (const uint32_t*)woh, (const uint32_t*)wol,
                                        bo, out_ptr, nullptr, nullptr, 1.0f);
}

// round 9
// speedup vs baseline: 1.1545x; 1.1545x over previous
#include <cuda_runtime.h>
#include <cuda_bf16.h>
#include <stdint.h>
#include <math.h>

#define B 2
#define S 2048
#define E 1024
#define H 16
#define D 64
#define MROWS (B*S)                   // 4096
#define KPAIRS 512                    // 1024 floats -> 512 bf16 pairs
#define OUT_ELEMS (B*S*E)             // 4194304
#define ATTN_ELEMS ((size_t)B*H*S*S)  // 134217728

// ------------------------- device scratch (no runtime alloc) -----------------
__device__ uint32_t g_xq_hi[MROWS*KPAIRS], g_xq_lo[MROWS*KPAIRS];
__device__ uint32_t g_xk_hi[MROWS*KPAIRS], g_xk_lo[MROWS*KPAIRS];
__device__ uint32_t g_xv_hi[MROWS*KPAIRS], g_xv_lo[MROWS*KPAIRS];
__device__ uint32_t g_wq_hi[E*KPAIRS],  g_wq_lo[E*KPAIRS];
__device__ uint32_t g_wk_hi[E*KPAIRS],  g_wk_lo[E*KPAIRS];
__device__ uint32_t g_wv_hi[E*KPAIRS],  g_wv_lo[E*KPAIRS];
__device__ uint32_t g_wo_hi[E*KPAIRS],  g_wo_lo[E*KPAIRS];
__device__ uint32_t g_qhi[B*H*S*(D/2)], g_qlo[B*H*S*(D/2)];   // packed (b,h,s,d/2)
__device__ uint32_t g_khi[B*H*S*(D/2)], g_klo[B*H*S*(D/2)];
__device__ float    g_v[B*H*S*D];                              // fp32 (b,h,s,d)
__device__ uint32_t g_vthi[B*H*D*(S/2)], g_vtlo[B*H*D*(S/2)];  // V^T packed [bh][d][s/2]
__device__ uint32_t g_chi[MROWS*KPAIRS], g_clo[MROWS*KPAIRS];  // ctx packed (b,s,e/2)
__device__ float    g_m[B*H*S], g_l[B*H*S];

// ------------------------------- helpers -------------------------------------
__device__ __forceinline__ void split_pack(float x0, float x1,
                                           uint32_t& hi, uint32_t& lo) {
    __nv_bfloat16 h0 = __float2bfloat16(x0);
    __nv_bfloat16 h1 = __float2bfloat16(x1);
    __nv_bfloat16 l0 = __float2bfloat16(x0 - __bfloat162float(h0));
    __nv_bfloat16 l1 = __float2bfloat16(x1 - __bfloat162float(h1));
    hi = ((uint32_t)__bfloat16_as_ushort(h1) << 16) | __bfloat16_as_ushort(h0);
    lo = ((uint32_t)__bfloat16_as_ushort(l1) << 16) | __bfloat16_as_ushort(l0);
}

__device__ __forceinline__ void mma_bf16(float* d, const uint32_t* a, const uint32_t* b) {
    asm volatile(
        "mma.sync.aligned.m16n8k16.row.col.f32.bf16.bf16.f32 "
        "{%0,%1,%2,%3},{%4,%5,%6,%7},{%8,%9},{%0,%1,%2,%3};\n"
        : "+f"(d[0]), "+f"(d[1]), "+f"(d[2]), "+f"(d[3])
        : "r"(a[0]), "r"(a[1]), "r"(a[2]), "r"(a[3]), "r"(b[0]), "r"(b[1]));
}

__device__ __forceinline__ void cp16(uint32_t saddr, const void* gptr) {
    asm volatile("cp.async.cg.shared.global [%0], [%1], 16;\n"
                 :: "r"(saddr), "l"(gptr));
}
#define CP_COMMIT() asm volatile("cp.async.commit_group;\n" ::: "memory")

// ------------------------- pack fp32 -> bf16 hi/lo pairs ---------------------
__global__ __launch_bounds__(256)
void pack3_kernel(const float* __restrict__ s0, const float* __restrict__ s1,
                  const float* __restrict__ s2,
                  uint32_t* __restrict__ h0, uint32_t* __restrict__ l0_,
                  uint32_t* __restrict__ h1, uint32_t* __restrict__ l1_,
                  uint32_t* __restrict__ h2, uint32_t* __restrict__ l2_,
                  int npairs)
{
    int i = blockIdx.x * 256 + threadIdx.x;
    if (i >= npairs) return;
    const float* src = (blockIdx.y == 0) ? s0 : (blockIdx.y == 1) ? s1 : s2;
    uint32_t* hi = (blockIdx.y == 0) ? h0 : (blockIdx.y == 1) ? h1 : h2;
    uint32_t* lo = (blockIdx.y == 0) ? l0_ : (blockIdx.y == 1) ? l1_ : l2_;
    float2 v = ((const float2*)src)[i];
    uint32_t h, l;
    split_pack(v.x, v.y, h, l);
    hi[i] = h; lo[i] = l;
}

__global__ __launch_bounds__(256)
void pack4_kernel(const float* __restrict__ s0, const float* __restrict__ s1,
                  const float* __restrict__ s2, const float* __restrict__ s3,
                  uint32_t* __restrict__ h0, uint32_t* __restrict__ l0_,
                  uint32_t* __restrict__ h1, uint32_t* __restrict__ l1_,
                  uint32_t* __restrict__ h2, uint32_t* __restrict__ l2_,
                  uint32_t* __restrict__ h3, uint32_t* __restrict__ l3_,
                  int npairs)
{
    int i = blockIdx.x * 256 + threadIdx.x;
    if (i >= npairs) return;
    const float* src = (blockIdx.y == 0) ? s0 : (blockIdx.y == 1) ? s1
                     : (blockIdx.y == 2) ? s2 : s3;
    uint32_t* hi = (blockIdx.y == 0) ? h0 : (blockIdx.y == 1) ? h1
                 : (blockIdx.y == 2) ? h2 : h3;
    uint32_t* lo = (blockIdx.y == 0) ? l0_ : (blockIdx.y == 1) ? l1_
                 : (blockIdx.y == 2) ? l2_ : l3_;
    float2 v = ((const float2*)src)[i];
    uint32_t h, l;
    split_pack(v.x, v.y, h, l);
    hi[i] = h; lo[i] = l;
}

// ------------------------------- GEMM ----------------------------------------
// C[m][n] = dot(A[m,:], W[n,:]) + bias[n], M=4096, N=1024, K=1024.
// cp.async double-buffered. At the mma.sync structural ceiling (R6-verified).
#define STRG 36   // 32 pairs + pad
#define AH_O 0
#define AL_O (128*STRG)
#define WH_O (256*STRG)
#define WL_O (256*STRG + 64*STRG)
#define STAGE_W (384*STRG)                 // words per stage = 13824
#define SMEM_G (2*STAGE_W*4)               // 110592 bytes

template <int MODE>
__global__ __launch_bounds__(256)
void gemm_tc(const uint32_t* __restrict__ Ahi, const uint32_t* __restrict__ Alo,
             const uint32_t* __restrict__ Whi, const uint32_t* __restrict__ Wlo,
             const float* __restrict__ bias,
             float* __restrict__ outf,
             uint32_t* __restrict__ outhi, uint32_t* __restrict__ outlo,
             float scale)
{
    extern __shared__ uint32_t sg[];
    const uint32_t sbase = (uint32_t)__cvta_generic_to_shared(sg);

    const int t = threadIdx.x, lane = t & 31, g = lane >> 2, tg = lane & 3;
    const int warp = t >> 5, wm = warp >> 1, wn = warp & 1;
    const int rowBase = blockIdx.y * 128, colBase = blockIdx.x * 64;

    auto issue = [&](int kt, int st) {
        const int kp0g = kt * 32;
        const uint32_t sb = sbase + (uint32_t)st * (STAGE_W * 4);
        #pragma unroll
        for (int r = 0; r < 4; r++) {
            int idx = t + r * 256;
            int row = idx >> 3, c4 = (idx & 7) << 2;
            cp16(sb + (AH_O + row*STRG + c4) * 4,
                 Ahi + (size_t)(rowBase + row) * KPAIRS + kp0g + c4);
            cp16(sb + (AL_O + row*STRG + c4) * 4,
                 Alo + (size_t)(rowBase + row) * KPAIRS + kp0g + c4);
        }
        #pragma unroll
        for (int r = 0; r < 2; r++) {
            int idx = t + r * 256;
            int row = idx >> 3, c4 = (idx & 7) << 2;
            cp16(sb + (WH_O + row*STRG + c4) * 4,
                 Whi + (size_t)(colBase + row) * KPAIRS + kp0g + c4);
            cp16(sb + (WL_O + row*STRG + c4) * 4,
                 Wlo + (size_t)(colBase + row) * KPAIRS + kp0g + c4);
        }
        CP_COMMIT();
    };

    float acc[2][4][4] = {};

    issue(0, 0);
    issue(1, 1);

    for (int kt = 0; kt < 16; kt++) {
        if (kt < 15) asm volatile("cp.async.wait_group 1;\n" ::: "memory");
        else         asm volatile("cp.async.wait_group 0;\n" ::: "memory");
        __syncthreads();

        const uint32_t* Ah = sg + (kt & 1) * STAGE_W + AH_O;
        const uint32_t* Al = sg + (kt & 1) * STAGE_W + AL_O;
        const uint32_t* Wh = sg + (kt & 1) * STAGE_W + WH_O;
        const uint32_t* Wl = sg + (kt & 1) * STAGE_W + WL_O;

        #pragma unroll
        for (int ks = 0; ks < 4; ks++) {
            const int kp0 = ks * 8;
            uint32_t ah[2][4], al[2][4];
            #pragma unroll
            for (int mt = 0; mt < 2; mt++) {
                int r0 = (wm*32 + mt*16 + g) * STRG + kp0 + tg;
                int r8 = r0 + 8 * STRG;
                ah[mt][0] = Ah[r0]; ah[mt][1] = Ah[r8];
                ah[mt][2] = Ah[r0+4]; ah[mt][3] = Ah[r8+4];
                al[mt][0] = Al[r0]; al[mt][1] = Al[r8];
                al[mt][2] = Al[r0+4]; al[mt][3] = Al[r8+4];
            }
            #pragma unroll
            for (int nt = 0; nt < 4; nt++) {
                int nb = (wn*32 + nt*8 + g) * STRG + kp0 + tg;
                uint32_t bh[2] = { Wh[nb], Wh[nb+4] };
                uint32_t bl[2] = { Wl[nb], Wl[nb+4] };
                #pragma unroll
                for (int mt = 0; mt < 2; mt++) {
                    mma_bf16(acc[mt][nt], ah[mt], bh);
                    mma_bf16(acc[mt][nt], al[mt], bh);
                    mma_bf16(acc[mt][nt], ah[mt], bl);
                }
            }
        }
        __syncthreads();
        if (kt + 2 < 16) issue(kt + 2, kt & 1);
    }

    #pragma unroll
    for (int mt = 0; mt < 2; mt++) {
        #pragma unroll
        for (int nt = 0; nt < 4; nt++) {
            int m0 = rowBase + wm*32 + mt*16 + g;
            int n  = colBase + wn*32 + nt*8 + 2*tg;
            float b0 = bias[n], b1 = bias[n+1];
            float v00 = (acc[mt][nt][0] + b0) * scale;
            float v01 = (acc[mt][nt][1] + b1) * scale;
            float v10 = (acc[mt][nt][2] + b0) * scale;
            float v11 = (acc[mt][nt][3] + b1) * scale;
            if (MODE == 0) {
                *(float2*)(outf + (size_t)m0 * 1024 + n)       = make_float2(v00, v01);
                *(float2*)(outf + (size_t)(m0 + 8) * 1024 + n) = make_float2(v10, v11);
            } else if (MODE == 1) {
                int hh = n >> 6, dp = (n >> 1) & 31;
                {
                    int bb = m0 >> 11, ss = m0 & 2047;
                    size_t p = ((size_t)(bb*H + hh)*S + ss) * (D/2) + dp;
                    uint32_t hw, lw; split_pack(v00, v01, hw, lw);
                    outhi[p] = hw; outlo[p] = lw;
                }
                {
                    int m8 = m0 + 8, bb = m8 >> 11, ss = m8 & 2047;
                    size_t p = ((size_t)(bb*H + hh)*S + ss) * (D/2) + dp;
                    uint32_t hw, lw; split_pack(v10, v11, hw, lw);
                    outhi[p] = hw; outlo[p] = lw;
                }
            } else { // MODE 2
                int hh = n >> 6, d = n & 63;
                {
                    int bb = m0 >> 11, ss = m0 & 2047;
                    *(float2*)(outf + ((size_t)(bb*H + hh)*S + ss) * D + d) = make_float2(v00, v01);
                }
                {
                    int m8 = m0 + 8, bb = m8 >> 11, ss = m8 & 2047;
                    *(float2*)(outf + ((size_t)(bb*H + hh)*S + ss) * D + d) = make_float2(v10, v11);
                }
            }
        }
    }
}

// --------------------- V transpose + split (one-shot) -------------------------
// g_v (b,h,s,d) fp32 -> Vt packed hi/lo [bh][d][s/2], pairs along s.
__global__ __launch_bounds__(256)
void vtrans_kernel(const float* __restrict__ vf,
                   uint32_t* __restrict__ vthi, uint32_t* __restrict__ vtlo)
{
    __shared__ float sm[64][65];
    const int t = threadIdx.x;
    const int bh = blockIdx.y, s0 = blockIdx.x * 64;
    const float* src = vf + ((size_t)bh * S + s0) * D;
    #pragma unroll
    for (int r = 0; r < 4; r++) {
        int idx = t + r * 256;               // 1024 float4 slots
        int row = idx >> 4, c4 = (idx & 15) << 2;
        float4 v = *(const float4*)(src + (size_t)row * D + c4);
        sm[row][c4] = v.x; sm[row][c4+1] = v.y; sm[row][c4+2] = v.z; sm[row][c4+3] = v.w;
    }
    __syncthreads();
    #pragma unroll
    for (int r = 0; r < 8; r++) {
        int slot = t + r * 256;              // 2048 = 64 d x 32 sp
        int d = slot >> 5, sp = slot & 31;
        uint32_t h, l;
        split_pack(sm[2*sp][d], sm[2*sp+1][d], h, l);
        size_t p = ((size_t)bh * D + d) * (S/2) + (s0 >> 1) + sp;
        vthi[p] = h; vtlo[p] = l;
    }
}

// ------------------------------- attention -----------------------------------
// Flash sweep + raw spill; norm kernel finalizes. K double-buffered cp.async,
// V single-buffered cp.async (awaited post-softmax). V pre-transposed/packed.
#define STRA 36
#define QH_W 0
#define QL_W 2304
#define KST_W 4608          // stage st at KST_W + st*4608; lo at +2304
#define VH_W 13824
#define VL_W 16128
#define PH_W 18432
#define PL_W 20736
#define PS_W 23040          // fp32 64x68
#define STRP 68
#define STAT_W 27392        // m 64 | l 64 | fac 64
#define SMEM_A2 (27584*4)   // 110336 bytes

__global__ __launch_bounds__(256)
void attn_tc(const uint32_t* __restrict__ qhi, const uint32_t* __restrict__ qlo,
             const uint32_t* __restrict__ khi, const uint32_t* __restrict__ klo,
             const uint32_t* __restrict__ vthi, const uint32_t* __restrict__ vtlo,
             float* __restrict__ attn_raw,
             float* __restrict__ gm, float* __restrict__ gl,
             uint32_t* __restrict__ ctxhi, uint32_t* __restrict__ ctxlo,
             int write_attn)
{
    extern __shared__ uint32_t sa[];
    const uint32_t sab = (uint32_t)__cvta_generic_to_shared(sa);
    uint32_t* Qh = sa + QH_W;
    uint32_t* Ql = sa + QL_W;
    uint32_t* Vh = sa + VH_W;
    uint32_t* Vl = sa + VL_W;
    uint32_t* Ph = sa + PH_W;
    uint32_t* Pl = sa + PL_W;
    float*    Ps = (float*)(sa + PS_W);
    float* m_run = (float*)(sa + STAT_W);
    float* l_run = m_run + 64;
    float* fac   = l_run + 64;

    const int qt = blockIdx.x, h = blockIdx.y, b = blockIdx.z;
    const int bh = b * H + h;
    const int t = threadIdx.x, lane = t & 31, g = lane >> 2, tg = lane & 3;
    const int warp = t >> 5, wm = warp >> 1, wn = warp & 1;

    // Q tile once
    {
        const size_t qb = ((size_t)bh * S + qt * 64) * (D/2);
        #pragma unroll
        for (int r = 0; r < 2; r++) {
            int idx = t + r * 256;
            int row = idx >> 3, c4 = (idx & 7) << 2;
            *(uint4*)&Qh[row*STRA + c4] = *(const uint4*)(qhi + qb + row*(D/2) + c4);
            *(uint4*)&Ql[row*STRA + c4] = *(const uint4*)(qlo + qb + row*(D/2) + c4);
        }
    }
    if (t < 64) { m_run[t] = -1e30f; l_run[t] = 0.0f; }

    // prologue: prefetch K(0) into stage 0
    {
        const size_t kb = ((size_t)bh * S) * (D/2);
        #pragma unroll
        for (int r = 0; r < 2; r++) {
            int idx = t + r * 256;
            int row = idx >> 3, c4 = (idx & 7) << 2;
            cp16(sab + (KST_W + row*STRA + c4)*4,        khi + kb + row*(D/2) + c4);
            cp16(sab + (KST_W + 2304 + row*STRA + c4)*4, klo + kb + row*(D/2) + c4);
        }
        CP_COMMIT();
    }

    float cacc[4][4] = {};

    for (int kt = 0; kt < S/64; kt++) {
        __syncthreads();   // PV(kt-1)/QK(kt-1) done: V buffer + K stage (kt+1)&1 reusable

        // issue V(kt)
        #pragma unroll
        for (int r = 0; r < 2; r++) {
            int idx = t + r * 256;
            int row = idx >> 3, c4 = (idx & 7) << 2;
            size_t vrow = ((size_t)bh * D + row) * (S/2) + kt*32;
            cp16(sab + (VH_W + row*STRA + c4)*4, vthi + vrow + c4);
            cp16(sab + (VL_W + row*STRA + c4)*4, vtlo + vrow + c4);
        }
        CP_COMMIT();
        // issue K(kt+1)
        if (kt + 1 < S/64) {
            const size_t kb = ((size_t)bh * S + (kt+1) * 64) * (D/2);
            const int st = (kt + 1) & 1;
            #pragma unroll
            for (int r = 0; r < 2; r++) {
                int idx = t + r * 256;
                int row = idx >> 3, c4 = (idx & 7) << 2;
                cp16(sab + (KST_W + st*4608 + row*STRA + c4)*4,        khi + kb + row*(D/2) + c4);
                cp16(sab + (KST_W + st*4608 + 2304 + row*STRA + c4)*4, klo + kb + row*(D/2) + c4);
            }
            CP_COMMIT();
        }

        // wait K(kt): newer groups = V(kt) [+ K(kt+1) if issued]
        if (kt + 1 < S/64) asm volatile("cp.async.wait_group 2;\n" ::: "memory");
        else               asm volatile("cp.async.wait_group 1;\n" ::: "memory");
        __syncthreads();

        const uint32_t* Khp = sa + KST_W + (kt & 1) * 4608;
        const uint32_t* Klp = Khp + 2304;

        // S = Q @ K^T (q pre-scaled)
        float sacc[4][4] = {};
        #pragma unroll
        for (int ks = 0; ks < 4; ks++) {
            const int kp0 = ks * 8;
            uint32_t ah[4], al[4];
            int r0 = (wm*16 + g) * STRA + kp0 + tg;
            int r8 = r0 + 8 * STRA;
            ah[0] = Qh[r0]; ah[1] = Qh[r8]; ah[2] = Qh[r0+4]; ah[3] = Qh[r8+4];
            al[0] = Ql[r0]; al[1] = Ql[r8]; al[2] = Ql[r0+4]; al[3] = Ql[r8+4];
            #pragma unroll
            for (int nt = 0; nt < 4; nt++) {
                int nb = (wn*32 + nt*8 + g) * STRA + kp0 + tg;
                uint32_t bhf[2] = { Khp[nb], Khp[nb+4] };
                uint32_t blf[2] = { Klp[nb], Klp[nb+4] };
                mma_bf16(sacc[nt], ah, bhf);
                mma_bf16(sacc[nt], al, bhf);
                mma_bf16(sacc[nt], ah, blf);
            }
        }
        #pragma unroll
        for (int nt = 0; nt < 4; nt++) {
            int rr = (wm*16 + g) * STRP + wn*32 + nt*8 + 2*tg;
            Ps[rr]            = sacc[nt][0];
            Ps[rr + 1]        = sacc[nt][1];
            Ps[rr + 8*STRP]   = sacc[nt][2];
            Ps[rr + 8*STRP+1] = sacc[nt][3];
        }
        __syncthreads();

        // spill raw scores
        if (write_attn) {
            #pragma unroll
            for (int r = 0; r < 4; r++) {
                int idx = t + r * 256;
                int row = idx >> 4, c4 = (idx & 15) << 2;
                float4 v = *(const float4*)(Ps + row*STRP + c4);
                *(float4*)(attn_raw + (size_t)bh*S*S
                           + (size_t)(qt*64 + row) * S + kt*64 + c4) = v;
            }
        }
        // online softmax: 4 threads per row; write split P
        {
            const int q = t >> 2, gg = t & 3;
            const float* prow = Ps + q * STRP;
            float mx = -1e30f;
            #pragma unroll
            for (int c = gg*16; c < gg*16 + 16; c++) mx = fmaxf(mx, prow[c]);
            mx = fmaxf(mx, __shfl_xor_sync(0xffffffffu, mx, 1));
            mx = fmaxf(mx, __shfl_xor_sync(0xffffffffu, mx, 2));
            const float m_old = m_run[q];
            const float m_new = fmaxf(m_old, mx);
            const float f = __expf(m_old - m_new);
            float sum = 0.0f;
            #pragma unroll
            for (int cp = 0; cp < 8; cp++) {
                float p0 = __expf(prow[gg*16 + 2*cp]     - m_new);
                float p1 = __expf(prow[gg*16 + 2*cp + 1] - m_new);
                sum += p0 + p1;
                uint32_t hw, lw; split_pack(p0, p1, hw, lw);
                Ph[q*STRA + gg*8 + cp] = hw;
                Pl[q*STRA + gg*8 + cp] = lw;
            }
            sum += __shfl_xor_sync(0xffffffffu, sum, 1);
            sum += __shfl_xor_sync(0xffffffffu, sum, 2);
            if (gg == 0) {
                m_run[q] = m_new;
                l_run[q] = l_run[q] * f + sum;
                fac[q]   = f;
            }
        }

        // wait V(kt): newer groups = K(kt+1) if issued
        if (kt + 1 < S/64) asm volatile("cp.async.wait_group 1;\n" ::: "memory");
        else               asm volatile("cp.async.wait_group 0;\n" ::: "memory");
        __syncthreads();

        // rescale + ctx += P @ V
        {
            float f0 = fac[wm*16 + g];
            float f8 = fac[wm*16 + g + 8];
            #pragma unroll
            for (int nt = 0; nt < 4; nt++) {
                cacc[nt][0] *= f0; cacc[nt][1] *= f0;
                cacc[nt][2] *= f8; cacc[nt][3] *= f8;
            }
        }
        #pragma unroll
        for (int ks = 0; ks < 4; ks++) {
            const int kp0 = ks * 8;
            uint32_t ah[4], al[4];
            int r0 = (wm*16 + g) * STRA + kp0 + tg;
            int r8 = r0 + 8 * STRA;
            ah[0] = Ph[r0]; ah[1] = Ph[r8]; ah[2] = Ph[r0+4]; ah[3] = Ph[r8+4];
            al[0] = Pl[r0]; al[1] = Pl[r8]; al[2] = Pl[r0+4]; al[3] = Pl[r8+4];
            #pragma unroll
            for (int nt = 0; nt < 4; nt++) {
                int nb = (wn*32 + nt*8 + g) * STRA + kp0 + tg;
                uint32_t bhf[2] = { Vh[nb], Vh[nb+4] };
                uint32_t blf[2] = { Vl[nb], Vl[nb+4] };
                mma_bf16(cacc[nt], ah, bhf);
                mma_bf16(cacc[nt], al, bhf);
                mma_bf16(cacc[nt], ah, blf);
            }
        }
    }

    // epilogue: normalize, split-pack ctx into (b,s,e/2)
    {
        float inv0 = 1.0f / l_run[wm*16 + g];
        float inv8 = 1.0f / l_run[wm*16 + g + 8];
        int s0 = qt*64 + wm*16 + g;
        #pragma unroll
        for (int nt = 0; nt < 4; nt++) {
            int pp = h * 32 + wn*16 + nt*4 + tg;
            uint32_t hw, lw;
            split_pack(cacc[nt][0]*inv0, cacc[nt][1]*inv0, hw, lw);
            size_t p0 = ((size_t)b*S + s0) * KPAIRS + pp;
            ctxhi[p0] = hw; ctxlo[p0] = lw;
            split_pack(cacc[nt][2]*inv8, cacc[nt][3]*inv8, hw, lw);
            size_t p8 = ((size_t)b*S + s0 + 8) * KPAIRS + pp;
            ctxhi[p8] = hw; ctxlo[p8] = lw;
        }
    }
    if (write_attn && t < 64) {
        gm[(size_t)bh*S + qt*64 + t] = m_run[t];
        gl[(size_t)bh*S + qt*64 + t] = l_run[t];
    }
}

// ---------------- normalize raw scores into probabilities --------------------
__global__ __launch_bounds__(256)
void norm_kernel(float* __restrict__ attn)
{
    const size_t i4 = (size_t)blockIdx.x * blockDim.x + threadIdx.x;
    if (i4 >= ATTN_ELEMS / 4) return;
    const size_t row = i4 >> 9;
    const float m = g_m[row];
    const float invl = 1.0f / g_l[row];
    float4 v = ((const float4*)attn)[i4];
    v.x = __expf(v.x - m) * invl;
    v.y = __expf(v.y - m) * invl;
    v.z = __expf(v.z - m) * invl;
    v.w = __expf(v.w - m) * invl;
    ((float4*)attn)[i4] = v;
}

// --------------------------------- launch ------------------------------------
extern "C" void kernel_launch(void* const* d_in, const int* in_sizes, int n_in,
                              void* d_out, int out_size)
{
    const float* query = (const float*)d_in[0];
    const float* key   = (const float*)d_in[1];
    const float* value = (const float*)d_in[2];
    const float* Wq = (const float*)d_in[3];
    const float* bq = (const float*)d_in[4];
    const float* Wk = (const float*)d_in[5];
    const float* bk = (const float*)d_in[6];
    const float* Wv = (const float*)d_in[7];
    const float* bv = (const float*)d_in[8];
    const float* Wo = (const float*)d_in[9];
    const float* bo = (const float*)d_in[10];

    float* out_ptr = (float*)d_out;
    const int write_attn = (out_size >= (int)(OUT_ELEMS + ATTN_ELEMS)) ? 1 : 0;
    float* attn_ptr = out_ptr + OUT_ELEMS;

    void* xqh; cudaGetSymbolAddress(&xqh, g_xq_hi);
    void* xql; cudaGetSymbolAddress(&xql, g_xq_lo);
    void* xkh; cudaGetSymbolAddress(&xkh, g_xk_hi);
    void* xkl; cudaGetSymbolAddress(&xkl, g_xk_lo);
    void* xvh; cudaGetSymbolAddress(&xvh, g_xv_hi);
    void* xvl; cudaGetSymbolAddress(&xvl, g_xv_lo);
    void* wqh; cudaGetSymbolAddress(&wqh, g_wq_hi);
    void* wql; cudaGetSymbolAddress(&wql, g_wq_lo);
    void* wkh; cudaGetSymbolAddress(&wkh, g_wk_hi);
    void* wkl; cudaGetSymbolAddress(&wkl, g_wk_lo);
    void* wvh; cudaGetSymbolAddress(&wvh, g_wv_hi);
    void* wvl; cudaGetSymbolAddress(&wvl, g_wv_lo);
    void* woh; cudaGetSymbolAddress(&woh, g_wo_hi);
    void* wol; cudaGetSymbolAddress(&wol, g_wo_lo);
    void* qh;  cudaGetSymbolAddress(&qh,  g_qhi);
    void* ql;  cudaGetSymbolAddress(&ql,  g_qlo);
    void* kh;  cudaGetSymbolAddress(&kh,  g_khi);
    void* kl;  cudaGetSymbolAddress(&kl,  g_klo);
    void* vv;  cudaGetSymbolAddress(&vv,  g_v);
    void* vth; cudaGetSymbolAddress(&vth, g_vthi);
    void* vtl; cudaGetSymbolAddress(&vtl, g_vtlo);
    void* ch;  cudaGetSymbolAddress(&ch,  g_chi);
    void* cl;  cudaGetSymbolAddress(&cl,  g_clo);
    void* mm;  cudaGetSymbolAddress(&mm,  g_m);
    void* ll;  cudaGetSymbolAddress(&ll,  g_l);

    const int npi = MROWS * KPAIRS;   // 2,097,152
    const int npw = E * KPAIRS;       // 524,288

    pack3_kernel<<<dim3(npi/256, 3), 256>>>(
        query, key, value,
        (uint32_t*)xqh, (uint32_t*)xql,
        (uint32_t*)xkh, (uint32_t*)xkl,
        (uint32_t*)xvh, (uint32_t*)xvl, npi);
    pack4_kernel<<<dim3(npw/256, 4), 256>>>(
        Wq, Wk, Wv, Wo,
        (uint32_t*)wqh, (uint32_t*)wql,
        (uint32_t*)wkh, (uint32_t*)wkl,
        (uint32_t*)wvh, (uint32_t*)wvl,
        (uint32_t*)woh, (uint32_t*)wol, npw);

    cudaFuncSetAttribute(gemm_tc<0>, cudaFuncAttributeMaxDynamicSharedMemorySize, SMEM_G);
    cudaFuncSetAttribute(gemm_tc<1>, cudaFuncAttributeMaxDynamicSharedMemorySize, SMEM_G);
    cudaFuncSetAttribute(gemm_tc<2>, cudaFuncAttributeMaxDynamicSharedMemorySize, SMEM_G);
    cudaFuncSetAttribute(attn_tc,    cudaFuncAttributeMaxDynamicSharedMemorySize, SMEM_A2);

    dim3 gblk(256);
    dim3 ggrid(1024/64, MROWS/128);   // (16, 32)

    gemm_tc<1><<<ggrid, gblk, SMEM_G>>>((const uint32_t*)xqh, (const uint32_t*)xql,
                                        (const uint32_t*)wqh, (const uint32_t*)wql,
                                        bq, nullptr, (uint32_t*)qh, (uint32_t*)ql, 0.125f);
    gemm_tc<1><<<ggrid, gblk, SMEM_G>>>((const uint32_t*)xkh, (const uint32_t*)xkl,
                                        (const uint32_t*)wkh, (const uint32_t*)wkl,
                                        bk, nullptr, (uint32_t*)kh, (uint32_t*)kl, 1.0f);
    gemm_tc<2><<<ggrid, gblk, SMEM_G>>>((const uint32_t*)xvh, (const uint32_t*)xvl,
                                        (const uint32_t*)wvh, (const uint32_t*)wvl,
                                        bv, (float*)vv, nullptr, nullptr, 1.0f);

    // V^T pack (replaces per-tile transpose inside attn)
    vtrans_kernel<<<dim3(S/64, B*H), 256>>>((const float*)vv,
                                            (uint32_t*)vth, (uint32_t*)vtl);

    dim3 agrid(S/64, H, B);
    attn_tc<<<agrid, gblk, SMEM_A2>>>((const uint32_t*)qh, (const uint32_t*)ql,
                                      (const uint32_t*)kh, (const uint32_t*)kl,
                                      (const uint32_t*)vth, (const uint32_t*)vtl,
                                      attn_ptr, (float*)mm, (float*)ll,
                                      (uint32_t*)ch, (uint32_t*)cl, write_attn);

    if (write_attn) {
        const size_t n4 = ATTN_ELEMS / 4;
        norm_kernel<<<(unsigned)((n4 + 255) / 256), 256>>>(attn_ptr);
    }

    gemm_tc<0><<<ggrid, gblk, SMEM_G>>>((const uint32_t*)ch, (const uint32_t*)cl,
                                        (const uint32_t*)woh, (const uint32_t*)wol,
                                        bo, out_ptr, nullptr, nullptr, 1.0f);
}